// round 12
// baseline (speedup 1.0000x reference)
#include <cuda_runtime.h>
#include <cuda_fp16.h>
#include <math.h>

#define Nn 50000
#define Ee 800000
#define Bb 512
#define Hh 128
#define Gg 32
#define EPSf 1e-5f

// ---------------- device scratch (static, no allocs) ----------------
__device__ __half g_hw16[(size_t)Nn * Hh]; // h @ W, fp16
__device__ float g_agg[(size_t)Nn * Hh];   // aggregated (pre-BN), fp32
__device__ float g_dinv[Nn];
__device__ int   g_deg[Nn];                // zeroed by scan_k after use
__device__ int   g_rowptr[Nn + 1];
__device__ int   g_cursor[Nn];
__device__ int   g_csr[Ee];                // src node per in-edge, bucketed by dst
__device__ float g_coef[Ee];               // dinv[s]*dinv[d] per in-edge (same order)
__device__ float g_stats3[3][2 * Hh];      // per-layer [sum, sumsq]; zeroed by mlp_k
__device__ float g_pool[Bb * Hh];          // zeroed by mlp_k after use
__device__ float g_cnt[Bb];                // zeroed by mlp_k after use

// ---------------- degree / dinv ----------------
__global__ void deg_count_k(const int* __restrict__ dst) {
    int i = blockIdx.x * blockDim.x + threadIdx.x;
    if (i < Ee) atomicAdd(&g_deg[dst[i]], 1);
}

__global__ void dinv_k() {
    int i = blockIdx.x * blockDim.x + threadIdx.x;
    if (i < Nn) g_dinv[i] = rsqrtf((float)(g_deg[i] + 1));  // +1 self loop
}

// ---------------- prefix scan over degrees (single block) ----------------
__global__ void scan_k() {
    const int T = 1024;
    const int C = (Nn + T - 1) / T;
    int tid = threadIdx.x;
    int b0 = tid * C;
    int b1 = min(b0 + C, Nn);
    int s = 0;
    for (int i = b0; i < b1; i++) s += g_deg[i];
    __shared__ int sh[T];
    sh[tid] = s;
    __syncthreads();
    for (int o = 1; o < T; o <<= 1) {
        int v = (tid >= o) ? sh[tid - o] : 0;
        __syncthreads();
        sh[tid] += v;
        __syncthreads();
    }
    int run = (tid > 0) ? sh[tid - 1] : 0;
    for (int i = b0; i < b1; i++) {
        g_rowptr[i] = run;
        g_cursor[i] = run;
        int d = g_deg[i];
        g_deg[i] = 0;                     // self-clean for next call
        run += d;
    }
    if (tid == T - 1) g_rowptr[Nn] = run;
}

// ---------------- CSR fill (bucket edges by dst; coef precomputed) ----------------
__global__ void fill_k(const int* __restrict__ src, const int* __restrict__ dst) {
    int e = blockIdx.x * blockDim.x + threadIdx.x;
    if (e >= Ee) return;
    int d = dst[e];
    int s = src[e];
    int pos = atomicAdd(&g_cursor[d], 1);
    g_csr[pos] = s;
    g_coef[pos] = g_dinv[s] * g_dinv[d];
}

// ---------------- fused gather + self-loop + bias + BN stats ----------------
__device__ __forceinline__ float4 ld_row16(const __half* row, int lane) {
    uint2 u = __ldg((const uint2*)row + lane);
    float2 f0 = __half22float2(*(__half2*)&u.x);
    float2 f1 = __half22float2(*(__half2*)&u.y);
    return make_float4(f0.x, f0.y, f1.x, f1.y);
}

#define NPW 8
__global__ void gather_k(const float* __restrict__ bias, int layer) {
    int tid = threadIdx.x;
    int lane = tid & 31;
    int wIn = tid >> 5;
    int gw = blockIdx.x * 8 + wIn;
    int n0 = gw * NPW;

    float4 bv = ((const float4*)bias)[lane];
    float bs0 = 0.f, bs1 = 0.f, bs2 = 0.f, bs3 = 0.f;
    float q0 = 0.f, q1 = 0.f, q2 = 0.f, q3 = 0.f;

    // preload node bounds (9) and self-dinv (8) for the whole warp
    int rp = 0;
    if (lane <= NPW) rp = g_rowptr[min(n0 + lane, Nn)];
    float dv = 0.f;
    if (lane < NPW) {
        int nd = n0 + lane;
        if (nd < Nn) dv = g_dinv[nd];
    }

    for (int ni = 0; ni < NPW; ni++) {
        int nd = n0 + ni;
        if (nd >= Nn) break;
        int ofs = __shfl_sync(0xFFFFFFFFu, rp, ni);
        int end = __shfl_sync(0xFFFFFFFFu, rp, ni + 1);
        float dd = __shfl_sync(0xFFFFFFFFu, dv, ni);
        float self = dd * dd;
        float4 hv = ld_row16(g_hw16 + (size_t)nd * Hh, lane);
        float4 a0, a1, a2, a3;
        a0.x = fmaf(self, hv.x, bv.x);
        a0.y = fmaf(self, hv.y, bv.y);
        a0.z = fmaf(self, hv.z, bv.z);
        a0.w = fmaf(self, hv.w, bv.w);
        a1 = make_float4(0.f, 0.f, 0.f, 0.f);
        a2 = make_float4(0.f, 0.f, 0.f, 0.f);
        a3 = make_float4(0.f, 0.f, 0.f, 0.f);

        // software-pipelined chunk loop (prefetch next chunk's csr/coef)
        int base = ofs;
        int cnt = min(32, end - base);
        int sidx = 0;
        float cf = 0.f;
        if (base < end && lane < cnt) {
            sidx = g_csr[base + lane];
            cf = g_coef[base + lane];
        }
        while (base < end) {
            int nbase = base + 32;
            int ncnt = min(32, end - nbase);
            int nsidx = 0;
            float ncf = 0.f;
            if (nbase < end && lane < ncnt) {
                nsidx = g_csr[nbase + lane];
                ncf = g_coef[nbase + lane];
            }

            int j = 0;
            for (; j + 8 <= cnt; j += 8) {
                int ss[8];
                float cc[8];
                #pragma unroll
                for (int u = 0; u < 8; u++) {
                    ss[u] = __shfl_sync(0xFFFFFFFFu, sidx, j + u);
                    cc[u] = __shfl_sync(0xFFFFFFFFu, cf, j + u);
                }
                uint2 raw[8];
                #pragma unroll
                for (int u = 0; u < 8; u++)
                    raw[u] = __ldg((const uint2*)(g_hw16 + (size_t)ss[u] * Hh) + lane);
                #pragma unroll
                for (int u = 0; u < 8; u += 4) {
                    #pragma unroll
                    for (int w = 0; w < 4; w++) {
                        float2 f0 = __half22float2(*(__half2*)&raw[u + w].x);
                        float2 f1 = __half22float2(*(__half2*)&raw[u + w].y);
                        float c = cc[u + w];
                        float4* ap = (w == 0) ? &a0 : (w == 1) ? &a1 : (w == 2) ? &a2 : &a3;
                        ap->x = fmaf(c, f0.x, ap->x);
                        ap->y = fmaf(c, f0.y, ap->y);
                        ap->z = fmaf(c, f1.x, ap->z);
                        ap->w = fmaf(c, f1.y, ap->w);
                    }
                }
            }
            for (; j + 4 <= cnt; j += 4) {
                int s0 = __shfl_sync(0xFFFFFFFFu, sidx, j + 0);
                int s1 = __shfl_sync(0xFFFFFFFFu, sidx, j + 1);
                int s2 = __shfl_sync(0xFFFFFFFFu, sidx, j + 2);
                int s3 = __shfl_sync(0xFFFFFFFFu, sidx, j + 3);
                float c0 = __shfl_sync(0xFFFFFFFFu, cf, j + 0);
                float c1 = __shfl_sync(0xFFFFFFFFu, cf, j + 1);
                float c2 = __shfl_sync(0xFFFFFFFFu, cf, j + 2);
                float c3 = __shfl_sync(0xFFFFFFFFu, cf, j + 3);
                float4 v0 = ld_row16(g_hw16 + (size_t)s0 * Hh, lane);
                float4 v1 = ld_row16(g_hw16 + (size_t)s1 * Hh, lane);
                float4 v2 = ld_row16(g_hw16 + (size_t)s2 * Hh, lane);
                float4 v3 = ld_row16(g_hw16 + (size_t)s3 * Hh, lane);
                a0.x = fmaf(c0, v0.x, a0.x); a0.y = fmaf(c0, v0.y, a0.y);
                a0.z = fmaf(c0, v0.z, a0.z); a0.w = fmaf(c0, v0.w, a0.w);
                a1.x = fmaf(c1, v1.x, a1.x); a1.y = fmaf(c1, v1.y, a1.y);
                a1.z = fmaf(c1, v1.z, a1.z); a1.w = fmaf(c1, v1.w, a1.w);
                a2.x = fmaf(c2, v2.x, a2.x); a2.y = fmaf(c2, v2.y, a2.y);
                a2.z = fmaf(c2, v2.z, a2.z); a2.w = fmaf(c2, v2.w, a2.w);
                a3.x = fmaf(c3, v3.x, a3.x); a3.y = fmaf(c3, v3.y, a3.y);
                a3.z = fmaf(c3, v3.z, a3.z); a3.w = fmaf(c3, v3.w, a3.w);
            }
            for (; j < cnt; j++) {
                int s = __shfl_sync(0xFFFFFFFFu, sidx, j);
                float c = __shfl_sync(0xFFFFFFFFu, cf, j);
                float4 v = ld_row16(g_hw16 + (size_t)s * Hh, lane);
                a0.x = fmaf(c, v.x, a0.x);
                a0.y = fmaf(c, v.y, a0.y);
                a0.z = fmaf(c, v.z, a0.z);
                a0.w = fmaf(c, v.w, a0.w);
            }

            base = nbase;
            cnt = ncnt;
            sidx = nsidx;
            cf = ncf;
        }

        float4 acc;
        acc.x = (a0.x + a1.x) + (a2.x + a3.x);
        acc.y = (a0.y + a1.y) + (a2.y + a3.y);
        acc.z = (a0.z + a1.z) + (a2.z + a3.z);
        acc.w = (a0.w + a1.w) + (a2.w + a3.w);
        ((float4*)(g_agg + (size_t)nd * Hh))[lane] = acc;

        bs0 += acc.x; bs1 += acc.y; bs2 += acc.z; bs3 += acc.w;
        q0 = fmaf(acc.x, acc.x, q0);
        q1 = fmaf(acc.y, acc.y, q1);
        q2 = fmaf(acc.z, acc.z, q2);
        q3 = fmaf(acc.w, acc.w, q3);
    }

    __shared__ float s_sum[Hh];
    __shared__ float s_ss[Hh];
    if (tid < Hh) { s_sum[tid] = 0.f; s_ss[tid] = 0.f; }
    __syncthreads();
    int c0i = lane * 4;
    atomicAdd(&s_sum[c0i + 0], bs0); atomicAdd(&s_ss[c0i + 0], q0);
    atomicAdd(&s_sum[c0i + 1], bs1); atomicAdd(&s_ss[c0i + 1], q1);
    atomicAdd(&s_sum[c0i + 2], bs2); atomicAdd(&s_ss[c0i + 2], q2);
    atomicAdd(&s_sum[c0i + 3], bs3); atomicAdd(&s_ss[c0i + 3], q3);
    __syncthreads();
    if (tid < Hh) {
        atomicAdd(&g_stats3[layer][tid], s_sum[tid]);
        atomicAdd(&g_stats3[layer][Hh + tid], s_ss[tid]);
    }
}

// ---------------- HMMA GEMM with in-kernel BN (from stats) ----------------
#define KS 136
#define GEMM_SMEM_H (2 * 128 * KS * (int)sizeof(__half))

__global__ void __launch_bounds__(256, 1)
gemm_hmma_k(const float* __restrict__ in, const float* __restrict__ W,
            const float* __restrict__ stats,      // null -> no BN
            const float* __restrict__ gamma, const float* __restrict__ beta) {
    extern __shared__ __half smh[];
    __half* As = smh;              // [128][KS]
    __half* Bs = smh + 128 * KS;   // [128][KS]
    __shared__ float sa[Hh], sc[Hh];
    int tid = threadIdx.x;
    int row0 = blockIdx.x * 128;

    if (stats) {
        if (tid < Hh) {
            float s = stats[tid], ss = stats[Hh + tid];
            float mean = s / (float)Nn;
            float var = ss / (float)Nn - mean * mean;
            float a = gamma[tid] * rsqrtf(var + EPSf);
            sa[tid] = a;
            sc[tid] = beta[tid] - mean * a;
        }
        __syncthreads();
    }

    // ---- load A: thread t handles row r=t>>1, cols 64*(t&1)..+63 ----
    {
        int r = tid >> 1;
        int ch = (tid & 1) * 64;
        int grow = row0 + r;
        __half* arow = As + r * KS + ch;
        if (grow < Nn) {
            const float4* rp = (const float4*)(in + (size_t)grow * Hh + ch);
            #pragma unroll
            for (int it = 0; it < 8; it++) {
                float4 v0 = __ldg(rp + it * 2);
                float4 v1 = __ldg(rp + it * 2 + 1);
                if (stats) {
                    int q = ch + it * 8;
                    float4 av0 = *(const float4*)(sa + q);
                    float4 cv0 = *(const float4*)(sc + q);
                    float4 av1 = *(const float4*)(sa + q + 4);
                    float4 cv1 = *(const float4*)(sc + q + 4);
                    v0.x = fmaxf(fmaf(v0.x, av0.x, cv0.x), 0.f);
                    v0.y = fmaxf(fmaf(v0.y, av0.y, cv0.y), 0.f);
                    v0.z = fmaxf(fmaf(v0.z, av0.z, cv0.z), 0.f);
                    v0.w = fmaxf(fmaf(v0.w, av0.w, cv0.w), 0.f);
                    v1.x = fmaxf(fmaf(v1.x, av1.x, cv1.x), 0.f);
                    v1.y = fmaxf(fmaf(v1.y, av1.y, cv1.y), 0.f);
                    v1.z = fmaxf(fmaf(v1.z, av1.z, cv1.z), 0.f);
                    v1.w = fmaxf(fmaf(v1.w, av1.w, cv1.w), 0.f);
                }
                __half2 h0 = __floats2half2_rn(v0.x, v0.y);
                __half2 h1 = __floats2half2_rn(v0.z, v0.w);
                __half2 h2 = __floats2half2_rn(v1.x, v1.y);
                __half2 h3 = __floats2half2_rn(v1.z, v1.w);
                uint4 o;
                o.x = *(unsigned*)&h0; o.y = *(unsigned*)&h1;
                o.z = *(unsigned*)&h2; o.w = *(unsigned*)&h3;
                *(uint4*)(arow + it * 8) = o;
            }
        } else {
            uint4 z = make_uint4(0, 0, 0, 0);
            #pragma unroll
            for (int it = 0; it < 8; it++) *(uint4*)(arow + it * 8) = z;
        }
    }

    // ---- load B = W^T: thread t: n = t&127, k range 64*(t>>7)..+63 ----
    {
        int n = tid & 127;
        int k0 = (tid >> 7) * 64;
        __half* brow = Bs + n * KS;
        #pragma unroll 8
        for (int k = k0; k < k0 + 64; k += 2) {
            float w0 = __ldg(W + (size_t)k * Hh + n);
            float w1 = __ldg(W + (size_t)(k + 1) * Hh + n);
            __half2 h = __floats2half2_rn(w0, w1);
            *(unsigned*)(brow + k) = *(unsigned*)&h;
        }
    }

    __syncthreads();

    // ---- compute ----
    int lane = tid & 31;
    int wrp = tid >> 5;
    int gid = lane >> 2;
    int tg = lane & 3;
    int m0 = wrp * 16;

    float c[16][4];
    #pragma unroll
    for (int nt = 0; nt < 16; nt++)
        #pragma unroll
        for (int i = 0; i < 4; i++) c[nt][i] = 0.f;

    const __half* aR0 = As + (m0 + gid) * KS + 2 * tg;
    const __half* aR1 = As + (m0 + gid + 8) * KS + 2 * tg;

    #pragma unroll
    for (int ki = 0; ki < 8; ki++) {
        int k0 = ki * 16;
        unsigned a0 = *(const unsigned*)(aR0 + k0);
        unsigned a1 = *(const unsigned*)(aR1 + k0);
        unsigned a2 = *(const unsigned*)(aR0 + k0 + 8);
        unsigned a3 = *(const unsigned*)(aR1 + k0 + 8);
        #pragma unroll
        for (int nt = 0; nt < 16; nt++) {
            const __half* bR = Bs + (nt * 8 + gid) * KS + 2 * tg;
            unsigned b0 = *(const unsigned*)(bR + k0);
            unsigned b1 = *(const unsigned*)(bR + k0 + 8);
            asm volatile(
                "mma.sync.aligned.m16n8k16.row.col.f32.f16.f16.f32 "
                "{%0,%1,%2,%3}, {%4,%5,%6,%7}, {%8,%9}, {%0,%1,%2,%3};"
                : "+f"(c[nt][0]), "+f"(c[nt][1]), "+f"(c[nt][2]), "+f"(c[nt][3])
                : "r"(a0), "r"(a1), "r"(a2), "r"(a3), "r"(b0), "r"(b1));
        }
    }

    // ---- epilogue: fp32 acc -> fp16 g_hw16 ----
    int r0g = row0 + m0 + gid;
    int r1g = r0g + 8;
    #pragma unroll
    for (int nt = 0; nt < 16; nt++) {
        int col = nt * 8 + 2 * tg;
        if (r0g < Nn) {
            __half2 h = __floats2half2_rn(c[nt][0], c[nt][1]);
            *(unsigned*)(g_hw16 + (size_t)r0g * Hh + col) = *(unsigned*)&h;
        }
        if (r1g < Nn) {
            __half2 h = __floats2half2_rn(c[nt][2], c[nt][3]);
            *(unsigned*)(g_hw16 + (size_t)r1g * Hh + col) = *(unsigned*)&h;
        }
    }
}

// ---------------- pooling (applies layer-3 BN+ReLU, computed from stats) ----------------
__global__ void pool_k(const int* __restrict__ batch,
                       const float* __restrict__ gamma, const float* __restrict__ beta) {
    __shared__ float sa[Hh], sc[Hh];
    int tid = threadIdx.x;
    if (tid < Hh) {
        float s = g_stats3[2][tid], ss = g_stats3[2][Hh + tid];
        float mean = s / (float)Nn;
        float var = ss / (float)Nn - mean * mean;
        float a = gamma[tid] * rsqrtf(var + EPSf);
        sa[tid] = a;
        sc[tid] = beta[tid] - mean * a;
    }
    __syncthreads();

    int gtid = blockIdx.x * blockDim.x + tid;
    int node = gtid >> 5;
    if (node >= Nn) return;
    int lane = gtid & 31;
    int b = __ldg(batch + node);
    float4 v = ((const float4*)(g_agg + (size_t)node * Hh))[lane];
    float4 av = *(const float4*)(sa + lane * 4);
    float4 cv = *(const float4*)(sc + lane * 4);
    float* o = g_pool + (size_t)b * Hh + lane * 4;
    atomicAdd(o + 0, fmaxf(fmaf(v.x, av.x, cv.x), 0.f));
    atomicAdd(o + 1, fmaxf(fmaf(v.y, av.y, cv.y), 0.f));
    atomicAdd(o + 2, fmaxf(fmaf(v.z, av.z, cv.z), 0.f));
    atomicAdd(o + 3, fmaxf(fmaf(v.w, av.w, cv.w), 0.f));
    if (lane == 0) atomicAdd(&g_cnt[b], 1.0f);
}

// ---------------- MLP head (also self-cleans pool/cnt/stats) ----------------
__global__ void mlp_k(const float* __restrict__ gf,
                      const float* __restrict__ M1w, const float* __restrict__ M1b,
                      const float* __restrict__ M2w, const float* __restrict__ M2b,
                      const float* __restrict__ M3w, const float* __restrict__ M3b,
                      float* __restrict__ out) {
    __shared__ float z[Hh + Gg];
    __shared__ float z1[128];
    __shared__ float z2[64];
    __shared__ float s_cnt;
    int b = blockIdx.x;
    int tid = threadIdx.x;
    if (b < 6 && tid < Hh) ((float*)g_stats3)[b * Hh + tid] = 0.f;   // zero 3x256 stats
    if (tid == 0) {
        s_cnt = fmaxf(g_cnt[b], 1.0f);
        g_cnt[b] = 0.f;
    }
    __syncthreads();
    float cnt = s_cnt;
    if (tid < Hh) {
        float pv = g_pool[(size_t)b * Hh + tid];
        g_pool[(size_t)b * Hh + tid] = 0.f;
        z[tid] = pv / cnt;
    }
    if (tid < Gg) z[Hh + tid] = gf[(size_t)b * Gg + tid];
    __syncthreads();
    {
        float acc = M1b[tid];
        #pragma unroll 4
        for (int k = 0; k < Hh + Gg; k++) acc = fmaf(z[k], M1w[k * 128 + tid], acc);
        z1[tid] = fmaxf(acc, 0.f);
    }
    __syncthreads();
    if (tid < 64) {
        float acc = M2b[tid];
        #pragma unroll 4
        for (int k = 0; k < 128; k++) acc = fmaf(z1[k], M2w[k * 64 + tid], acc);
        z2[tid] = fmaxf(acc, 0.f);
    }
    __syncthreads();
    if (tid == 0) {
        float acc = M3b[0];
        #pragma unroll 4
        for (int k = 0; k < 64; k++) acc = fmaf(z2[k], M3w[k], acc);
        out[b] = acc;
    }
}

// ---------------- host launch ----------------
extern "C" void kernel_launch(void* const* d_in, const int* in_sizes, int n_in,
                              void* d_out, int out_size) {
    const float* x   = (const float*)d_in[0];
    const int*   ei  = (const int*)d_in[1];
    const int*   batch = (const int*)d_in[2];
    const float* gf  = (const float*)d_in[3];
    const float* Wl[3]  = { (const float*)d_in[4],  (const float*)d_in[8],  (const float*)d_in[12] };
    const float* bl[3]  = { (const float*)d_in[5],  (const float*)d_in[9],  (const float*)d_in[13] };
    const float* gl[3]  = { (const float*)d_in[6],  (const float*)d_in[10], (const float*)d_in[14] };
    const float* bel[3] = { (const float*)d_in[7],  (const float*)d_in[11], (const float*)d_in[15] };
    const float* M1w = (const float*)d_in[16];
    const float* M1b = (const float*)d_in[17];
    const float* M2w = (const float*)d_in[18];
    const float* M2b = (const float*)d_in[19];
    const float* M3w = (const float*)d_in[20];
    const float* M3b = (const float*)d_in[21];
    float* out = (float*)d_out;

    const int* src = ei;
    const int* dst = ei + Ee;

    void *p_agg, *p_stats;
    cudaGetSymbolAddress(&p_agg, g_agg);
    cudaGetSymbolAddress(&p_stats, g_stats3);

    static int inited = 0;
    static cudaStream_t s2;
    static cudaEvent_t evF, evJ;
    if (!inited) {
        cudaFuncSetAttribute(gemm_hmma_k, cudaFuncAttributeMaxDynamicSharedMemorySize, GEMM_SMEM_H);
        cudaStreamCreateWithFlags(&s2, cudaStreamNonBlocking);
        cudaEventCreateWithFlags(&evF, cudaEventDisableTiming);
        cudaEventCreateWithFlags(&evJ, cudaEventDisableTiming);
        inited = 1;
    }

    const int gemm_blocks = (Nn + 127) / 128;                  // 391
    const int gather_blocks = (Nn + 8 * NPW - 1) / (8 * NPW);
    const int pool_blocks = (Nn * 32 + 255) / 256;

    // Fork: CSR build on side stream, layer-0 GEMM (independent) on main stream.
    cudaEventRecord(evF, 0);
    cudaStreamWaitEvent(s2, evF, 0);
    deg_count_k<<<(Ee + 255) / 256, 256, 0, s2>>>(dst);
    dinv_k<<<(Nn + 255) / 256, 256, 0, s2>>>();
    scan_k<<<1, 1024, 0, s2>>>();
    fill_k<<<(Ee + 255) / 256, 256, 0, s2>>>(src, dst);

    gemm_hmma_k<<<gemm_blocks, 256, GEMM_SMEM_H>>>(x, Wl[0], 0, 0, 0);

    cudaEventRecord(evJ, s2);
    cudaStreamWaitEvent(0, evJ, 0);

    for (int l = 0; l < 3; l++) {
        if (l > 0)
            gemm_hmma_k<<<gemm_blocks, 256, GEMM_SMEM_H>>>(
                (const float*)p_agg, Wl[l],
                (const float*)p_stats + (size_t)(l - 1) * 2 * Hh, gl[l - 1], bel[l - 1]);
        gather_k<<<gather_blocks, 256>>>(bl[l], l);
    }

    pool_k<<<pool_blocks, 256>>>(batch, gl[2], bel[2]);
    mlp_k<<<Bb, 128>>>(gf, M1w, M1b, M2w, M2b, M3w, M3b, out);
}

// round 13
// speedup vs baseline: 1.0992x; 1.0992x over previous
#include <cuda_runtime.h>
#include <cuda_fp16.h>
#include <math.h>

#define Nn 50000
#define Ee 800000
#define Bb 512
#define Hh 128
#define Gg 32
#define EPSf 1e-5f

// ---------------- device scratch (static, no allocs) ----------------
__device__ __half g_hw16[(size_t)Nn * Hh]; // h @ W, fp16
__device__ float g_agg[(size_t)Nn * Hh];   // aggregated (pre-BN), fp32
__device__ float g_dinv[Nn];
__device__ int   g_deg[Nn];                // zeroed by scan_k after use
__device__ int   g_rowptr[Nn + 1];
__device__ int   g_cursor[Nn];
__device__ int   g_csr[Ee];                // src node per in-edge, bucketed by dst
__device__ int   g_bptr[Bb + 1];           // batch -> node range (batch is sorted)
__device__ float g_stats3[3][2 * Hh];      // per-layer [sum, sumsq]; zeroed by mlp_k
__device__ float g_pool[Bb * Hh];          // fully overwritten by pool2_k each call

// ---------------- degree / dinv ----------------
__global__ void deg_count_k(const int* __restrict__ dst) {
    int i = blockIdx.x * blockDim.x + threadIdx.x;
    if (i < Ee) atomicAdd(&g_deg[dst[i]], 1);
}

__global__ void dinv_k() {
    int i = blockIdx.x * blockDim.x + threadIdx.x;
    if (i < Nn) g_dinv[i] = rsqrtf((float)(g_deg[i] + 1));  // +1 self loop
}

// ---------------- batch rowptr (batch sorted): bptr[b] = first i with batch[i] >= b
__global__ void batch_ptr_k(const int* __restrict__ batch) {
    int i = blockIdx.x * blockDim.x + threadIdx.x;
    if (i > Nn) return;
    if (i == 0) {
        int b0 = batch[0];
        for (int b = 0; b <= b0; b++) g_bptr[b] = 0;
    } else if (i == Nn) {
        int bl = batch[Nn - 1];
        for (int b = bl + 1; b <= Bb; b++) g_bptr[b] = Nn;
    } else {
        int bp = batch[i - 1];
        int bc = batch[i];
        for (int b = bp + 1; b <= bc; b++) g_bptr[b] = i;
    }
}

// ---------------- prefix scan over degrees (single block) ----------------
__global__ void scan_k() {
    const int T = 1024;
    const int C = (Nn + T - 1) / T;
    int tid = threadIdx.x;
    int b0 = tid * C;
    int b1 = min(b0 + C, Nn);
    int s = 0;
    for (int i = b0; i < b1; i++) s += g_deg[i];
    __shared__ int sh[T];
    sh[tid] = s;
    __syncthreads();
    for (int o = 1; o < T; o <<= 1) {
        int v = (tid >= o) ? sh[tid - o] : 0;
        __syncthreads();
        sh[tid] += v;
        __syncthreads();
    }
    int run = (tid > 0) ? sh[tid - 1] : 0;
    for (int i = b0; i < b1; i++) {
        g_rowptr[i] = run;
        g_cursor[i] = run;
        int d = g_deg[i];
        g_deg[i] = 0;                     // self-clean for next call
        run += d;
    }
    if (tid == T - 1) g_rowptr[Nn] = run;
}

// ---------------- CSR fill (bucket edges by dst) ----------------
__global__ void fill_k(const int* __restrict__ src, const int* __restrict__ dst) {
    int e = blockIdx.x * blockDim.x + threadIdx.x;
    if (e >= Ee) return;
    int d = dst[e];
    int pos = atomicAdd(&g_cursor[d], 1);
    g_csr[pos] = src[e];
}

// ---------------- fused gather + self-loop + bias + BN stats (R11 structure) ----------------
__device__ __forceinline__ float4 ld_row16(const __half* row, int lane) {
    uint2 u = __ldg((const uint2*)row + lane);
    float2 f0 = __half22float2(*(__half2*)&u.x);
    float2 f1 = __half22float2(*(__half2*)&u.y);
    return make_float4(f0.x, f0.y, f1.x, f1.y);
}

#define NPW 8
__global__ void gather_k(const float* __restrict__ bias, int layer) {
    int tid = threadIdx.x;
    int lane = tid & 31;
    int wIn = tid >> 5;
    int gw = blockIdx.x * 8 + wIn;
    int n0 = gw * NPW;

    float4 bv = ((const float4*)bias)[lane];
    float bs0 = 0.f, bs1 = 0.f, bs2 = 0.f, bs3 = 0.f;
    float q0 = 0.f, q1 = 0.f, q2 = 0.f, q3 = 0.f;

    for (int nd = n0; nd < min(n0 + NPW, Nn); nd++) {
        float dd = g_dinv[nd];
        float self = dd * dd;
        float4 hv = ld_row16(g_hw16 + (size_t)nd * Hh, lane);
        float4 a0, a1, a2, a3;
        a0.x = fmaf(self, hv.x, bv.x);
        a0.y = fmaf(self, hv.y, bv.y);
        a0.z = fmaf(self, hv.z, bv.z);
        a0.w = fmaf(self, hv.w, bv.w);
        a1 = make_float4(0.f, 0.f, 0.f, 0.f);
        a2 = make_float4(0.f, 0.f, 0.f, 0.f);
        a3 = make_float4(0.f, 0.f, 0.f, 0.f);

        int ofs = g_rowptr[nd];
        int end = g_rowptr[nd + 1];
        for (int base = ofs; base < end; base += 32) {
            int cnt = min(32, end - base);
            int sidx = 0;
            float sdi = 0.f;
            if (lane < cnt) {
                sidx = g_csr[base + lane];
                sdi = g_dinv[sidx];
            }
            int j = 0;
            for (; j + 8 <= cnt; j += 8) {
                int ss[8];
                float cc[8];
                #pragma unroll
                for (int u = 0; u < 8; u++) {
                    ss[u] = __shfl_sync(0xFFFFFFFFu, sidx, j + u);
                    cc[u] = __shfl_sync(0xFFFFFFFFu, sdi, j + u) * dd;
                }
                uint2 raw[8];
                #pragma unroll
                for (int u = 0; u < 8; u++)
                    raw[u] = __ldg((const uint2*)(g_hw16 + (size_t)ss[u] * Hh) + lane);
                #pragma unroll
                for (int u = 0; u < 8; u += 4) {
                    #pragma unroll
                    for (int w = 0; w < 4; w++) {
                        float2 f0 = __half22float2(*(__half2*)&raw[u + w].x);
                        float2 f1 = __half22float2(*(__half2*)&raw[u + w].y);
                        float c = cc[u + w];
                        float4* ap = (w == 0) ? &a0 : (w == 1) ? &a1 : (w == 2) ? &a2 : &a3;
                        ap->x = fmaf(c, f0.x, ap->x);
                        ap->y = fmaf(c, f0.y, ap->y);
                        ap->z = fmaf(c, f1.x, ap->z);
                        ap->w = fmaf(c, f1.y, ap->w);
                    }
                }
            }
            for (; j + 4 <= cnt; j += 4) {
                int s0 = __shfl_sync(0xFFFFFFFFu, sidx, j + 0);
                int s1 = __shfl_sync(0xFFFFFFFFu, sidx, j + 1);
                int s2 = __shfl_sync(0xFFFFFFFFu, sidx, j + 2);
                int s3 = __shfl_sync(0xFFFFFFFFu, sidx, j + 3);
                float c0 = __shfl_sync(0xFFFFFFFFu, sdi, j + 0) * dd;
                float c1 = __shfl_sync(0xFFFFFFFFu, sdi, j + 1) * dd;
                float c2 = __shfl_sync(0xFFFFFFFFu, sdi, j + 2) * dd;
                float c3 = __shfl_sync(0xFFFFFFFFu, sdi, j + 3) * dd;
                float4 v0 = ld_row16(g_hw16 + (size_t)s0 * Hh, lane);
                float4 v1 = ld_row16(g_hw16 + (size_t)s1 * Hh, lane);
                float4 v2 = ld_row16(g_hw16 + (size_t)s2 * Hh, lane);
                float4 v3 = ld_row16(g_hw16 + (size_t)s3 * Hh, lane);
                a0.x = fmaf(c0, v0.x, a0.x); a0.y = fmaf(c0, v0.y, a0.y);
                a0.z = fmaf(c0, v0.z, a0.z); a0.w = fmaf(c0, v0.w, a0.w);
                a1.x = fmaf(c1, v1.x, a1.x); a1.y = fmaf(c1, v1.y, a1.y);
                a1.z = fmaf(c1, v1.z, a1.z); a1.w = fmaf(c1, v1.w, a1.w);
                a2.x = fmaf(c2, v2.x, a2.x); a2.y = fmaf(c2, v2.y, a2.y);
                a2.z = fmaf(c2, v2.z, a2.z); a2.w = fmaf(c2, v2.w, a2.w);
                a3.x = fmaf(c3, v3.x, a3.x); a3.y = fmaf(c3, v3.y, a3.y);
                a3.z = fmaf(c3, v3.z, a3.z); a3.w = fmaf(c3, v3.w, a3.w);
            }
            for (; j < cnt; j++) {
                int s = __shfl_sync(0xFFFFFFFFu, sidx, j);
                float c = __shfl_sync(0xFFFFFFFFu, sdi, j) * dd;
                float4 v = ld_row16(g_hw16 + (size_t)s * Hh, lane);
                a0.x = fmaf(c, v.x, a0.x);
                a0.y = fmaf(c, v.y, a0.y);
                a0.z = fmaf(c, v.z, a0.z);
                a0.w = fmaf(c, v.w, a0.w);
            }
        }
        float4 acc;
        acc.x = (a0.x + a1.x) + (a2.x + a3.x);
        acc.y = (a0.y + a1.y) + (a2.y + a3.y);
        acc.z = (a0.z + a1.z) + (a2.z + a3.z);
        acc.w = (a0.w + a1.w) + (a2.w + a3.w);
        ((float4*)(g_agg + (size_t)nd * Hh))[lane] = acc;

        bs0 += acc.x; bs1 += acc.y; bs2 += acc.z; bs3 += acc.w;
        q0 = fmaf(acc.x, acc.x, q0);
        q1 = fmaf(acc.y, acc.y, q1);
        q2 = fmaf(acc.z, acc.z, q2);
        q3 = fmaf(acc.w, acc.w, q3);
    }

    __shared__ float s_sum[Hh];
    __shared__ float s_ss[Hh];
    if (tid < Hh) { s_sum[tid] = 0.f; s_ss[tid] = 0.f; }
    __syncthreads();
    int c0i = lane * 4;
    atomicAdd(&s_sum[c0i + 0], bs0); atomicAdd(&s_ss[c0i + 0], q0);
    atomicAdd(&s_sum[c0i + 1], bs1); atomicAdd(&s_ss[c0i + 1], q1);
    atomicAdd(&s_sum[c0i + 2], bs2); atomicAdd(&s_ss[c0i + 2], q2);
    atomicAdd(&s_sum[c0i + 3], bs3); atomicAdd(&s_ss[c0i + 3], q3);
    __syncthreads();
    if (tid < Hh) {
        atomicAdd(&g_stats3[layer][tid], s_sum[tid]);
        atomicAdd(&g_stats3[layer][Hh + tid], s_ss[tid]);
    }
}

// ---------------- HMMA GEMM with in-kernel BN (from stats) ----------------
#define KS 136
#define GEMM_SMEM_H (2 * 128 * KS * (int)sizeof(__half))

__global__ void __launch_bounds__(256, 1)
gemm_hmma_k(const float* __restrict__ in, const float* __restrict__ W,
            const float* __restrict__ stats,      // null -> no BN
            const float* __restrict__ gamma, const float* __restrict__ beta) {
    extern __shared__ __half smh[];
    __half* As = smh;              // [128][KS]
    __half* Bs = smh + 128 * KS;   // [128][KS]
    __shared__ float sa[Hh], sc[Hh];
    int tid = threadIdx.x;
    int row0 = blockIdx.x * 128;

    if (stats) {
        if (tid < Hh) {
            float s = stats[tid], ss = stats[Hh + tid];
            float mean = s / (float)Nn;
            float var = ss / (float)Nn - mean * mean;
            float a = gamma[tid] * rsqrtf(var + EPSf);
            sa[tid] = a;
            sc[tid] = beta[tid] - mean * a;
        }
        __syncthreads();
    }

    // ---- load A: thread t handles row r=t>>1, cols 64*(t&1)..+63 ----
    {
        int r = tid >> 1;
        int ch = (tid & 1) * 64;
        int grow = row0 + r;
        __half* arow = As + r * KS + ch;
        if (grow < Nn) {
            const float4* rp = (const float4*)(in + (size_t)grow * Hh + ch);
            #pragma unroll
            for (int it = 0; it < 8; it++) {
                float4 v0 = __ldg(rp + it * 2);
                float4 v1 = __ldg(rp + it * 2 + 1);
                if (stats) {
                    int q = ch + it * 8;
                    float4 av0 = *(const float4*)(sa + q);
                    float4 cv0 = *(const float4*)(sc + q);
                    float4 av1 = *(const float4*)(sa + q + 4);
                    float4 cv1 = *(const float4*)(sc + q + 4);
                    v0.x = fmaxf(fmaf(v0.x, av0.x, cv0.x), 0.f);
                    v0.y = fmaxf(fmaf(v0.y, av0.y, cv0.y), 0.f);
                    v0.z = fmaxf(fmaf(v0.z, av0.z, cv0.z), 0.f);
                    v0.w = fmaxf(fmaf(v0.w, av0.w, cv0.w), 0.f);
                    v1.x = fmaxf(fmaf(v1.x, av1.x, cv1.x), 0.f);
                    v1.y = fmaxf(fmaf(v1.y, av1.y, cv1.y), 0.f);
                    v1.z = fmaxf(fmaf(v1.z, av1.z, cv1.z), 0.f);
                    v1.w = fmaxf(fmaf(v1.w, av1.w, cv1.w), 0.f);
                }
                __half2 h0 = __floats2half2_rn(v0.x, v0.y);
                __half2 h1 = __floats2half2_rn(v0.z, v0.w);
                __half2 h2 = __floats2half2_rn(v1.x, v1.y);
                __half2 h3 = __floats2half2_rn(v1.z, v1.w);
                uint4 o;
                o.x = *(unsigned*)&h0; o.y = *(unsigned*)&h1;
                o.z = *(unsigned*)&h2; o.w = *(unsigned*)&h3;
                *(uint4*)(arow + it * 8) = o;
            }
        } else {
            uint4 z = make_uint4(0, 0, 0, 0);
            #pragma unroll
            for (int it = 0; it < 8; it++) *(uint4*)(arow + it * 8) = z;
        }
    }

    // ---- load B = W^T: thread t: n = t&127, k range 64*(t>>7)..+63 ----
    {
        int n = tid & 127;
        int k0 = (tid >> 7) * 64;
        __half* brow = Bs + n * KS;
        #pragma unroll 8
        for (int k = k0; k < k0 + 64; k += 2) {
            float w0 = __ldg(W + (size_t)k * Hh + n);
            float w1 = __ldg(W + (size_t)(k + 1) * Hh + n);
            __half2 h = __floats2half2_rn(w0, w1);
            *(unsigned*)(brow + k) = *(unsigned*)&h;
        }
    }

    __syncthreads();

    // ---- compute ----
    int lane = tid & 31;
    int wrp = tid >> 5;
    int gid = lane >> 2;
    int tg = lane & 3;
    int m0 = wrp * 16;

    float c[16][4];
    #pragma unroll
    for (int nt = 0; nt < 16; nt++)
        #pragma unroll
        for (int i = 0; i < 4; i++) c[nt][i] = 0.f;

    const __half* aR0 = As + (m0 + gid) * KS + 2 * tg;
    const __half* aR1 = As + (m0 + gid + 8) * KS + 2 * tg;

    #pragma unroll
    for (int ki = 0; ki < 8; ki++) {
        int k0 = ki * 16;
        unsigned a0 = *(const unsigned*)(aR0 + k0);
        unsigned a1 = *(const unsigned*)(aR1 + k0);
        unsigned a2 = *(const unsigned*)(aR0 + k0 + 8);
        unsigned a3 = *(const unsigned*)(aR1 + k0 + 8);
        #pragma unroll
        for (int nt = 0; nt < 16; nt++) {
            const __half* bR = Bs + (nt * 8 + gid) * KS + 2 * tg;
            unsigned b0 = *(const unsigned*)(bR + k0);
            unsigned b1 = *(const unsigned*)(bR + k0 + 8);
            asm volatile(
                "mma.sync.aligned.m16n8k16.row.col.f32.f16.f16.f32 "
                "{%0,%1,%2,%3}, {%4,%5,%6,%7}, {%8,%9}, {%0,%1,%2,%3};"
                : "+f"(c[nt][0]), "+f"(c[nt][1]), "+f"(c[nt][2]), "+f"(c[nt][3])
                : "r"(a0), "r"(a1), "r"(a2), "r"(a3), "r"(b0), "r"(b1));
        }
    }

    // ---- epilogue: fp32 acc -> fp16 g_hw16 ----
    int r0g = row0 + m0 + gid;
    int r1g = r0g + 8;
    #pragma unroll
    for (int nt = 0; nt < 16; nt++) {
        int col = nt * 8 + 2 * tg;
        if (r0g < Nn) {
            __half2 h = __floats2half2_rn(c[nt][0], c[nt][1]);
            *(unsigned*)(g_hw16 + (size_t)r0g * Hh + col) = *(unsigned*)&h;
        }
        if (r1g < Nn) {
            __half2 h = __floats2half2_rn(c[nt][2], c[nt][3]);
            *(unsigned*)(g_hw16 + (size_t)r1g * Hh + col) = *(unsigned*)&h;
        }
    }
}

// ---------------- pooling: segmented reduction over sorted batch (no atomics) ----------------
__global__ void pool2_k(const float* __restrict__ gamma, const float* __restrict__ beta) {
    __shared__ float sa[Hh], sc[Hh];
    int b = blockIdx.x;
    int tid = threadIdx.x;   // 128 threads, one per column
    {
        float s = g_stats3[2][tid], ss = g_stats3[2][Hh + tid];
        float mean = s / (float)Nn;
        float var = ss / (float)Nn - mean * mean;
        float a = gamma[tid] * rsqrtf(var + EPSf);
        sa[tid] = a;
        sc[tid] = beta[tid] - mean * a;
    }
    __syncthreads();

    int r0 = g_bptr[b];
    int r1 = g_bptr[b + 1];
    float a = sa[tid], cs = sc[tid];
    float acc0 = 0.f, acc1 = 0.f;
    int r = r0;
    for (; r + 2 <= r1; r += 2) {
        float v0 = g_agg[(size_t)r * Hh + tid];
        float v1 = g_agg[(size_t)(r + 1) * Hh + tid];
        acc0 += fmaxf(fmaf(v0, a, cs), 0.f);
        acc1 += fmaxf(fmaf(v1, a, cs), 0.f);
    }
    if (r < r1) acc0 += fmaxf(fmaf(g_agg[(size_t)r * Hh + tid], a, cs), 0.f);
    float cnt = fmaxf((float)(r1 - r0), 1.0f);
    g_pool[(size_t)b * Hh + tid] = (acc0 + acc1) / cnt;
}

// ---------------- MLP head (self-cleans stats) ----------------
__global__ void mlp_k(const float* __restrict__ gf,
                      const float* __restrict__ M1w, const float* __restrict__ M1b,
                      const float* __restrict__ M2w, const float* __restrict__ M2b,
                      const float* __restrict__ M3w, const float* __restrict__ M3b,
                      float* __restrict__ out) {
    __shared__ float z[Hh + Gg];
    __shared__ float z1[128];
    __shared__ float z2[64];
    int b = blockIdx.x;
    int tid = threadIdx.x;
    if (b < 6 && tid < Hh) ((float*)g_stats3)[b * Hh + tid] = 0.f;   // zero 3x256 stats
    if (tid < Hh) z[tid] = g_pool[(size_t)b * Hh + tid];
    if (tid < Gg) z[Hh + tid] = gf[(size_t)b * Gg + tid];
    __syncthreads();
    {
        float acc = M1b[tid];
        #pragma unroll 4
        for (int k = 0; k < Hh + Gg; k++) acc = fmaf(z[k], M1w[k * 128 + tid], acc);
        z1[tid] = fmaxf(acc, 0.f);
    }
    __syncthreads();
    if (tid < 64) {
        float acc = M2b[tid];
        #pragma unroll 4
        for (int k = 0; k < 128; k++) acc = fmaf(z1[k], M2w[k * 64 + tid], acc);
        z2[tid] = fmaxf(acc, 0.f);
    }
    __syncthreads();
    if (tid == 0) {
        float acc = M3b[0];
        #pragma unroll 4
        for (int k = 0; k < 64; k++) acc = fmaf(z2[k], M3w[k], acc);
        out[b] = acc;
    }
}

// ---------------- host launch ----------------
extern "C" void kernel_launch(void* const* d_in, const int* in_sizes, int n_in,
                              void* d_out, int out_size) {
    const float* x   = (const float*)d_in[0];
    const int*   ei  = (const int*)d_in[1];
    const int*   batch = (const int*)d_in[2];
    const float* gf  = (const float*)d_in[3];
    const float* Wl[3]  = { (const float*)d_in[4],  (const float*)d_in[8],  (const float*)d_in[12] };
    const float* bl[3]  = { (const float*)d_in[5],  (const float*)d_in[9],  (const float*)d_in[13] };
    const float* gl[3]  = { (const float*)d_in[6],  (const float*)d_in[10], (const float*)d_in[14] };
    const float* bel[3] = { (const float*)d_in[7],  (const float*)d_in[11], (const float*)d_in[15] };
    const float* M1w = (const float*)d_in[16];
    const float* M1b = (const float*)d_in[17];
    const float* M2w = (const float*)d_in[18];
    const float* M2b = (const float*)d_in[19];
    const float* M3w = (const float*)d_in[20];
    const float* M3b = (const float*)d_in[21];
    float* out = (float*)d_out;

    const int* src = ei;
    const int* dst = ei + Ee;

    void *p_agg, *p_stats;
    cudaGetSymbolAddress(&p_agg, g_agg);
    cudaGetSymbolAddress(&p_stats, g_stats3);

    static int inited = 0;
    static cudaStream_t s2;
    static cudaEvent_t evF, evJ;
    if (!inited) {
        cudaFuncSetAttribute(gemm_hmma_k, cudaFuncAttributeMaxDynamicSharedMemorySize, GEMM_SMEM_H);
        cudaStreamCreateWithFlags(&s2, cudaStreamNonBlocking);
        cudaEventCreateWithFlags(&evF, cudaEventDisableTiming);
        cudaEventCreateWithFlags(&evJ, cudaEventDisableTiming);
        inited = 1;
    }

    const int gemm_blocks = (Nn + 127) / 128;                  // 391
    const int gather_blocks = (Nn + 8 * NPW - 1) / (8 * NPW);
    const int bptr_blocks = (Nn + 1 + 255) / 256;

    // Fork: CSR build + batch rowptr on side stream, layer-0 GEMM on main stream.
    cudaEventRecord(evF, 0);
    cudaStreamWaitEvent(s2, evF, 0);
    deg_count_k<<<(Ee + 255) / 256, 256, 0, s2>>>(dst);
    dinv_k<<<(Nn + 255) / 256, 256, 0, s2>>>();
    scan_k<<<1, 1024, 0, s2>>>();
    fill_k<<<(Ee + 255) / 256, 256, 0, s2>>>(src, dst);
    batch_ptr_k<<<bptr_blocks, 256, 0, s2>>>(batch);

    gemm_hmma_k<<<gemm_blocks, 256, GEMM_SMEM_H>>>(x, Wl[0], 0, 0, 0);

    cudaEventRecord(evJ, s2);
    cudaStreamWaitEvent(0, evJ, 0);

    for (int l = 0; l < 3; l++) {
        if (l > 0)
            gemm_hmma_k<<<gemm_blocks, 256, GEMM_SMEM_H>>>(
                (const float*)p_agg, Wl[l],
                (const float*)p_stats + (size_t)(l - 1) * 2 * Hh, gl[l - 1], bel[l - 1]);
        gather_k<<<gather_blocks, 256>>>(bl[l], l);
    }

    pool2_k<<<Bb, Hh>>>(gl[2], bel[2]);
    mlp_k<<<Bb, 128>>>(gf, M1w, M1b, M2w, M2b, M3w, M3b, out);
}

// round 14
// speedup vs baseline: 1.1225x; 1.0212x over previous
#include <cuda_runtime.h>
#include <cuda_fp16.h>
#include <math.h>

#define Nn 50000
#define Ee 800000
#define Bb 512
#define Hh 128
#define Gg 32
#define EPSf 1e-5f

// ---------------- device scratch (static, no allocs) ----------------
__device__ __half g_hw16[(size_t)Nn * Hh]; // h @ W, fp16
__device__ float g_agg[(size_t)Nn * Hh];   // aggregated (pre-BN), fp32
__device__ float g_dinv[Nn];
__device__ int   g_deg[Nn];                // zeroed by scan_k after use
__device__ int   g_rowptr[Nn + 1];
__device__ int   g_cursor[Nn];
__device__ int   g_csr[Ee];                // src node per in-edge, bucketed by dst
__device__ float g_coef[Ee];               // dinv[s]*dinv[d], same bucket order
__device__ int   g_bptr[Bb + 1];           // batch -> node range (batch is sorted)
__device__ float g_stats3[3][2 * Hh];      // per-layer [sum, sumsq]; zeroed by mlp_k
__device__ float g_pool[Bb * Hh];          // fully overwritten by pool2_k each call

// ---------------- degree / dinv ----------------
__global__ void deg_count_k(const int* __restrict__ dst) {
    int i = blockIdx.x * blockDim.x + threadIdx.x;
    if (i < Ee) atomicAdd(&g_deg[dst[i]], 1);
}

__global__ void dinv_k() {
    int i = blockIdx.x * blockDim.x + threadIdx.x;
    if (i < Nn) g_dinv[i] = rsqrtf((float)(g_deg[i] + 1));  // +1 self loop
}

// ---------------- batch rowptr (batch sorted): bptr[b] = first i with batch[i] >= b
__global__ void batch_ptr_k(const int* __restrict__ batch) {
    int i = blockIdx.x * blockDim.x + threadIdx.x;
    if (i > Nn) return;
    if (i == 0) {
        int b0 = batch[0];
        for (int b = 0; b <= b0; b++) g_bptr[b] = 0;
    } else if (i == Nn) {
        int bl = batch[Nn - 1];
        for (int b = bl + 1; b <= Bb; b++) g_bptr[b] = Nn;
    } else {
        int bp = batch[i - 1];
        int bc = batch[i];
        for (int b = bp + 1; b <= bc; b++) g_bptr[b] = i;
    }
}

// ---------------- prefix scan over degrees (single block) ----------------
__global__ void scan_k() {
    const int T = 1024;
    const int C = (Nn + T - 1) / T;
    int tid = threadIdx.x;
    int b0 = tid * C;
    int b1 = min(b0 + C, Nn);
    int s = 0;
    for (int i = b0; i < b1; i++) s += g_deg[i];
    __shared__ int sh[T];
    sh[tid] = s;
    __syncthreads();
    for (int o = 1; o < T; o <<= 1) {
        int v = (tid >= o) ? sh[tid - o] : 0;
        __syncthreads();
        sh[tid] += v;
        __syncthreads();
    }
    int run = (tid > 0) ? sh[tid - 1] : 0;
    for (int i = b0; i < b1; i++) {
        g_rowptr[i] = run;
        g_cursor[i] = run;
        int d = g_deg[i];
        g_deg[i] = 0;                     // self-clean for next call
        run += d;
    }
    if (tid == T - 1) g_rowptr[Nn] = run;
}

// ---------------- CSR fill (bucket edges by dst; coef precomputed) ----------------
__global__ void fill_k(const int* __restrict__ src, const int* __restrict__ dst) {
    int e = blockIdx.x * blockDim.x + threadIdx.x;
    if (e >= Ee) return;
    int d = dst[e];
    int s = src[e];
    int pos = atomicAdd(&g_cursor[d], 1);
    g_csr[pos] = s;
    g_coef[pos] = g_dinv[s] * g_dinv[d];
}

// ---------------- fused gather + self-loop + bias + BN stats ----------------
// R11/R13 skeleton; only change: coalesced g_coef load replaces the dependent
// random g_dinv[sidx] gather.
__device__ __forceinline__ float4 ld_row16(const __half* row, int lane) {
    uint2 u = __ldg((const uint2*)row + lane);
    float2 f0 = __half22float2(*(__half2*)&u.x);
    float2 f1 = __half22float2(*(__half2*)&u.y);
    return make_float4(f0.x, f0.y, f1.x, f1.y);
}

#define NPW 8
__global__ void gather_k(const float* __restrict__ bias, int layer) {
    int tid = threadIdx.x;
    int lane = tid & 31;
    int wIn = tid >> 5;
    int gw = blockIdx.x * 8 + wIn;
    int n0 = gw * NPW;

    float4 bv = ((const float4*)bias)[lane];
    float bs0 = 0.f, bs1 = 0.f, bs2 = 0.f, bs3 = 0.f;
    float q0 = 0.f, q1 = 0.f, q2 = 0.f, q3 = 0.f;

    for (int nd = n0; nd < min(n0 + NPW, Nn); nd++) {
        float dd = g_dinv[nd];
        float self = dd * dd;
        float4 hv = ld_row16(g_hw16 + (size_t)nd * Hh, lane);
        float4 a0, a1, a2, a3;
        a0.x = fmaf(self, hv.x, bv.x);
        a0.y = fmaf(self, hv.y, bv.y);
        a0.z = fmaf(self, hv.z, bv.z);
        a0.w = fmaf(self, hv.w, bv.w);
        a1 = make_float4(0.f, 0.f, 0.f, 0.f);
        a2 = make_float4(0.f, 0.f, 0.f, 0.f);
        a3 = make_float4(0.f, 0.f, 0.f, 0.f);

        int ofs = g_rowptr[nd];
        int end = g_rowptr[nd + 1];
        for (int base = ofs; base < end; base += 32) {
            int cnt = min(32, end - base);
            int sidx = 0;
            float cfv = 0.f;
            if (lane < cnt) {
                sidx = g_csr[base + lane];
                cfv = g_coef[base + lane];     // independent, coalesced
            }
            int j = 0;
            for (; j + 8 <= cnt; j += 8) {
                int ss[8];
                float cc[8];
                #pragma unroll
                for (int u = 0; u < 8; u++) {
                    ss[u] = __shfl_sync(0xFFFFFFFFu, sidx, j + u);
                    cc[u] = __shfl_sync(0xFFFFFFFFu, cfv, j + u);
                }
                uint2 raw[8];
                #pragma unroll
                for (int u = 0; u < 8; u++)
                    raw[u] = __ldg((const uint2*)(g_hw16 + (size_t)ss[u] * Hh) + lane);
                #pragma unroll
                for (int u = 0; u < 8; u += 4) {
                    #pragma unroll
                    for (int w = 0; w < 4; w++) {
                        float2 f0 = __half22float2(*(__half2*)&raw[u + w].x);
                        float2 f1 = __half22float2(*(__half2*)&raw[u + w].y);
                        float c = cc[u + w];
                        float4* ap = (w == 0) ? &a0 : (w == 1) ? &a1 : (w == 2) ? &a2 : &a3;
                        ap->x = fmaf(c, f0.x, ap->x);
                        ap->y = fmaf(c, f0.y, ap->y);
                        ap->z = fmaf(c, f1.x, ap->z);
                        ap->w = fmaf(c, f1.y, ap->w);
                    }
                }
            }
            for (; j + 4 <= cnt; j += 4) {
                int s0 = __shfl_sync(0xFFFFFFFFu, sidx, j + 0);
                int s1 = __shfl_sync(0xFFFFFFFFu, sidx, j + 1);
                int s2 = __shfl_sync(0xFFFFFFFFu, sidx, j + 2);
                int s3 = __shfl_sync(0xFFFFFFFFu, sidx, j + 3);
                float c0 = __shfl_sync(0xFFFFFFFFu, cfv, j + 0);
                float c1 = __shfl_sync(0xFFFFFFFFu, cfv, j + 1);
                float c2 = __shfl_sync(0xFFFFFFFFu, cfv, j + 2);
                float c3 = __shfl_sync(0xFFFFFFFFu, cfv, j + 3);
                float4 v0 = ld_row16(g_hw16 + (size_t)s0 * Hh, lane);
                float4 v1 = ld_row16(g_hw16 + (size_t)s1 * Hh, lane);
                float4 v2 = ld_row16(g_hw16 + (size_t)s2 * Hh, lane);
                float4 v3 = ld_row16(g_hw16 + (size_t)s3 * Hh, lane);
                a0.x = fmaf(c0, v0.x, a0.x); a0.y = fmaf(c0, v0.y, a0.y);
                a0.z = fmaf(c0, v0.z, a0.z); a0.w = fmaf(c0, v0.w, a0.w);
                a1.x = fmaf(c1, v1.x, a1.x); a1.y = fmaf(c1, v1.y, a1.y);
                a1.z = fmaf(c1, v1.z, a1.z); a1.w = fmaf(c1, v1.w, a1.w);
                a2.x = fmaf(c2, v2.x, a2.x); a2.y = fmaf(c2, v2.y, a2.y);
                a2.z = fmaf(c2, v2.z, a2.z); a2.w = fmaf(c2, v2.w, a2.w);
                a3.x = fmaf(c3, v3.x, a3.x); a3.y = fmaf(c3, v3.y, a3.y);
                a3.z = fmaf(c3, v3.z, a3.z); a3.w = fmaf(c3, v3.w, a3.w);
            }
            for (; j < cnt; j++) {
                int s = __shfl_sync(0xFFFFFFFFu, sidx, j);
                float c = __shfl_sync(0xFFFFFFFFu, cfv, j);
                float4 v = ld_row16(g_hw16 + (size_t)s * Hh, lane);
                a0.x = fmaf(c, v.x, a0.x);
                a0.y = fmaf(c, v.y, a0.y);
                a0.z = fmaf(c, v.z, a0.z);
                a0.w = fmaf(c, v.w, a0.w);
            }
        }
        float4 acc;
        acc.x = (a0.x + a1.x) + (a2.x + a3.x);
        acc.y = (a0.y + a1.y) + (a2.y + a3.y);
        acc.z = (a0.z + a1.z) + (a2.z + a3.z);
        acc.w = (a0.w + a1.w) + (a2.w + a3.w);
        ((float4*)(g_agg + (size_t)nd * Hh))[lane] = acc;

        bs0 += acc.x; bs1 += acc.y; bs2 += acc.z; bs3 += acc.w;
        q0 = fmaf(acc.x, acc.x, q0);
        q1 = fmaf(acc.y, acc.y, q1);
        q2 = fmaf(acc.z, acc.z, q2);
        q3 = fmaf(acc.w, acc.w, q3);
    }

    __shared__ float s_sum[Hh];
    __shared__ float s_ss[Hh];
    if (tid < Hh) { s_sum[tid] = 0.f; s_ss[tid] = 0.f; }
    __syncthreads();
    int c0i = lane * 4;
    atomicAdd(&s_sum[c0i + 0], bs0); atomicAdd(&s_ss[c0i + 0], q0);
    atomicAdd(&s_sum[c0i + 1], bs1); atomicAdd(&s_ss[c0i + 1], q1);
    atomicAdd(&s_sum[c0i + 2], bs2); atomicAdd(&s_ss[c0i + 2], q2);
    atomicAdd(&s_sum[c0i + 3], bs3); atomicAdd(&s_ss[c0i + 3], q3);
    __syncthreads();
    if (tid < Hh) {
        atomicAdd(&g_stats3[layer][tid], s_sum[tid]);
        atomicAdd(&g_stats3[layer][Hh + tid], s_ss[tid]);
    }
}

// ---------------- HMMA GEMM with in-kernel BN (from stats) ----------------
#define KS 136
#define GEMM_SMEM_H (2 * 128 * KS * (int)sizeof(__half))

__global__ void __launch_bounds__(256, 1)
gemm_hmma_k(const float* __restrict__ in, const float* __restrict__ W,
            const float* __restrict__ stats,      // null -> no BN
            const float* __restrict__ gamma, const float* __restrict__ beta) {
    extern __shared__ __half smh[];
    __half* As = smh;              // [128][KS]
    __half* Bs = smh + 128 * KS;   // [128][KS]
    __shared__ float sa[Hh], sc[Hh];
    int tid = threadIdx.x;
    int row0 = blockIdx.x * 128;

    if (stats) {
        if (tid < Hh) {
            float s = stats[tid], ss = stats[Hh + tid];
            float mean = s / (float)Nn;
            float var = ss / (float)Nn - mean * mean;
            float a = gamma[tid] * rsqrtf(var + EPSf);
            sa[tid] = a;
            sc[tid] = beta[tid] - mean * a;
        }
        __syncthreads();
    }

    // ---- load A: thread t handles row r=t>>1, cols 64*(t&1)..+63 ----
    {
        int r = tid >> 1;
        int ch = (tid & 1) * 64;
        int grow = row0 + r;
        __half* arow = As + r * KS + ch;
        if (grow < Nn) {
            const float4* rp = (const float4*)(in + (size_t)grow * Hh + ch);
            #pragma unroll
            for (int it = 0; it < 8; it++) {
                float4 v0 = __ldg(rp + it * 2);
                float4 v1 = __ldg(rp + it * 2 + 1);
                if (stats) {
                    int q = ch + it * 8;
                    float4 av0 = *(const float4*)(sa + q);
                    float4 cv0 = *(const float4*)(sc + q);
                    float4 av1 = *(const float4*)(sa + q + 4);
                    float4 cv1 = *(const float4*)(sc + q + 4);
                    v0.x = fmaxf(fmaf(v0.x, av0.x, cv0.x), 0.f);
                    v0.y = fmaxf(fmaf(v0.y, av0.y, cv0.y), 0.f);
                    v0.z = fmaxf(fmaf(v0.z, av0.z, cv0.z), 0.f);
                    v0.w = fmaxf(fmaf(v0.w, av0.w, cv0.w), 0.f);
                    v1.x = fmaxf(fmaf(v1.x, av1.x, cv1.x), 0.f);
                    v1.y = fmaxf(fmaf(v1.y, av1.y, cv1.y), 0.f);
                    v1.z = fmaxf(fmaf(v1.z, av1.z, cv1.z), 0.f);
                    v1.w = fmaxf(fmaf(v1.w, av1.w, cv1.w), 0.f);
                }
                __half2 h0 = __floats2half2_rn(v0.x, v0.y);
                __half2 h1 = __floats2half2_rn(v0.z, v0.w);
                __half2 h2 = __floats2half2_rn(v1.x, v1.y);
                __half2 h3 = __floats2half2_rn(v1.z, v1.w);
                uint4 o;
                o.x = *(unsigned*)&h0; o.y = *(unsigned*)&h1;
                o.z = *(unsigned*)&h2; o.w = *(unsigned*)&h3;
                *(uint4*)(arow + it * 8) = o;
            }
        } else {
            uint4 z = make_uint4(0, 0, 0, 0);
            #pragma unroll
            for (int it = 0; it < 8; it++) *(uint4*)(arow + it * 8) = z;
        }
    }

    // ---- load B = W^T: thread t: n = t&127, k range 64*(t>>7)..+63 ----
    {
        int n = tid & 127;
        int k0 = (tid >> 7) * 64;
        __half* brow = Bs + n * KS;
        #pragma unroll 8
        for (int k = k0; k < k0 + 64; k += 2) {
            float w0 = __ldg(W + (size_t)k * Hh + n);
            float w1 = __ldg(W + (size_t)(k + 1) * Hh + n);
            __half2 h = __floats2half2_rn(w0, w1);
            *(unsigned*)(brow + k) = *(unsigned*)&h;
        }
    }

    __syncthreads();

    // ---- compute ----
    int lane = tid & 31;
    int wrp = tid >> 5;
    int gid = lane >> 2;
    int tg = lane & 3;
    int m0 = wrp * 16;

    float c[16][4];
    #pragma unroll
    for (int nt = 0; nt < 16; nt++)
        #pragma unroll
        for (int i = 0; i < 4; i++) c[nt][i] = 0.f;

    const __half* aR0 = As + (m0 + gid) * KS + 2 * tg;
    const __half* aR1 = As + (m0 + gid + 8) * KS + 2 * tg;

    #pragma unroll
    for (int ki = 0; ki < 8; ki++) {
        int k0 = ki * 16;
        unsigned a0 = *(const unsigned*)(aR0 + k0);
        unsigned a1 = *(const unsigned*)(aR1 + k0);
        unsigned a2 = *(const unsigned*)(aR0 + k0 + 8);
        unsigned a3 = *(const unsigned*)(aR1 + k0 + 8);
        #pragma unroll
        for (int nt = 0; nt < 16; nt++) {
            const __half* bR = Bs + (nt * 8 + gid) * KS + 2 * tg;
            unsigned b0 = *(const unsigned*)(bR + k0);
            unsigned b1 = *(const unsigned*)(bR + k0 + 8);
            asm volatile(
                "mma.sync.aligned.m16n8k16.row.col.f32.f16.f16.f32 "
                "{%0,%1,%2,%3}, {%4,%5,%6,%7}, {%8,%9}, {%0,%1,%2,%3};"
                : "+f"(c[nt][0]), "+f"(c[nt][1]), "+f"(c[nt][2]), "+f"(c[nt][3])
                : "r"(a0), "r"(a1), "r"(a2), "r"(a3), "r"(b0), "r"(b1));
        }
    }

    // ---- epilogue: fp32 acc -> fp16 g_hw16 ----
    int r0g = row0 + m0 + gid;
    int r1g = r0g + 8;
    #pragma unroll
    for (int nt = 0; nt < 16; nt++) {
        int col = nt * 8 + 2 * tg;
        if (r0g < Nn) {
            __half2 h = __floats2half2_rn(c[nt][0], c[nt][1]);
            *(unsigned*)(g_hw16 + (size_t)r0g * Hh + col) = *(unsigned*)&h;
        }
        if (r1g < Nn) {
            __half2 h = __floats2half2_rn(c[nt][2], c[nt][3]);
            *(unsigned*)(g_hw16 + (size_t)r1g * Hh + col) = *(unsigned*)&h;
        }
    }
}

// ---------------- pooling: segmented reduction over sorted batch (no atomics) ----------------
__global__ void pool2_k(const float* __restrict__ gamma, const float* __restrict__ beta) {
    __shared__ float sa[Hh], sc[Hh];
    int b = blockIdx.x;
    int tid = threadIdx.x;   // 128 threads, one per column
    {
        float s = g_stats3[2][tid], ss = g_stats3[2][Hh + tid];
        float mean = s / (float)Nn;
        float var = ss / (float)Nn - mean * mean;
        float a = gamma[tid] * rsqrtf(var + EPSf);
        sa[tid] = a;
        sc[tid] = beta[tid] - mean * a;
    }
    __syncthreads();

    int r0 = g_bptr[b];
    int r1 = g_bptr[b + 1];
    float a = sa[tid], cs = sc[tid];
    float acc0 = 0.f, acc1 = 0.f;
    int r = r0;
    for (; r + 2 <= r1; r += 2) {
        float v0 = g_agg[(size_t)r * Hh + tid];
        float v1 = g_agg[(size_t)(r + 1) * Hh + tid];
        acc0 += fmaxf(fmaf(v0, a, cs), 0.f);
        acc1 += fmaxf(fmaf(v1, a, cs), 0.f);
    }
    if (r < r1) acc0 += fmaxf(fmaf(g_agg[(size_t)r * Hh + tid], a, cs), 0.f);
    float cnt = fmaxf((float)(r1 - r0), 1.0f);
    g_pool[(size_t)b * Hh + tid] = (acc0 + acc1) / cnt;
}

// ---------------- MLP head (self-cleans stats) ----------------
__global__ void mlp_k(const float* __restrict__ gf,
                      const float* __restrict__ M1w, const float* __restrict__ M1b,
                      const float* __restrict__ M2w, const float* __restrict__ M2b,
                      const float* __restrict__ M3w, const float* __restrict__ M3b,
                      float* __restrict__ out) {
    __shared__ float z[Hh + Gg];
    __shared__ float z1[128];
    __shared__ float z2[64];
    int b = blockIdx.x;
    int tid = threadIdx.x;
    if (b < 6 && tid < Hh) ((float*)g_stats3)[b * Hh + tid] = 0.f;   // zero 3x256 stats
    if (tid < Hh) z[tid] = g_pool[(size_t)b * Hh + tid];
    if (tid < Gg) z[Hh + tid] = gf[(size_t)b * Gg + tid];
    __syncthreads();
    {
        float acc = M1b[tid];
        #pragma unroll 4
        for (int k = 0; k < Hh + Gg; k++) acc = fmaf(z[k], M1w[k * 128 + tid], acc);
        z1[tid] = fmaxf(acc, 0.f);
    }
    __syncthreads();
    if (tid < 64) {
        float acc = M2b[tid];
        #pragma unroll 4
        for (int k = 0; k < 128; k++) acc = fmaf(z1[k], M2w[k * 64 + tid], acc);
        z2[tid] = fmaxf(acc, 0.f);
    }
    __syncthreads();
    if (tid == 0) {
        float acc = M3b[0];
        #pragma unroll 4
        for (int k = 0; k < 64; k++) acc = fmaf(z2[k], M3w[k], acc);
        out[b] = acc;
    }
}

// ---------------- host launch ----------------
extern "C" void kernel_launch(void* const* d_in, const int* in_sizes, int n_in,
                              void* d_out, int out_size) {
    const float* x   = (const float*)d_in[0];
    const int*   ei  = (const int*)d_in[1];
    const int*   batch = (const int*)d_in[2];
    const float* gf  = (const float*)d_in[3];
    const float* Wl[3]  = { (const float*)d_in[4],  (const float*)d_in[8],  (const float*)d_in[12] };
    const float* bl[3]  = { (const float*)d_in[5],  (const float*)d_in[9],  (const float*)d_in[13] };
    const float* gl[3]  = { (const float*)d_in[6],  (const float*)d_in[10], (const float*)d_in[14] };
    const float* bel[3] = { (const float*)d_in[7],  (const float*)d_in[11], (const float*)d_in[15] };
    const float* M1w = (const float*)d_in[16];
    const float* M1b = (const float*)d_in[17];
    const float* M2w = (const float*)d_in[18];
    const float* M2b = (const float*)d_in[19];
    const float* M3w = (const float*)d_in[20];
    const float* M3b = (const float*)d_in[21];
    float* out = (float*)d_out;

    const int* src = ei;
    const int* dst = ei + Ee;

    void *p_agg, *p_stats;
    cudaGetSymbolAddress(&p_agg, g_agg);
    cudaGetSymbolAddress(&p_stats, g_stats3);

    static int inited = 0;
    static cudaStream_t s2;
    static cudaEvent_t evF, evJ;
    if (!inited) {
        cudaFuncSetAttribute(gemm_hmma_k, cudaFuncAttributeMaxDynamicSharedMemorySize, GEMM_SMEM_H);
        cudaStreamCreateWithFlags(&s2, cudaStreamNonBlocking);
        cudaEventCreateWithFlags(&evF, cudaEventDisableTiming);
        cudaEventCreateWithFlags(&evJ, cudaEventDisableTiming);
        inited = 1;
    }

    const int gemm_blocks = (Nn + 127) / 128;                  // 391
    const int gather_blocks = (Nn + 8 * NPW - 1) / (8 * NPW);
    const int bptr_blocks = (Nn + 1 + 255) / 256;

    // Fork: CSR build + batch rowptr on side stream, layer-0 GEMM on main stream.
    cudaEventRecord(evF, 0);
    cudaStreamWaitEvent(s2, evF, 0);
    deg_count_k<<<(Ee + 255) / 256, 256, 0, s2>>>(dst);
    dinv_k<<<(Nn + 255) / 256, 256, 0, s2>>>();
    scan_k<<<1, 1024, 0, s2>>>();
    fill_k<<<(Ee + 255) / 256, 256, 0, s2>>>(src, dst);
    batch_ptr_k<<<bptr_blocks, 256, 0, s2>>>(batch);

    gemm_hmma_k<<<gemm_blocks, 256, GEMM_SMEM_H>>>(x, Wl[0], 0, 0, 0);

    cudaEventRecord(evJ, s2);
    cudaStreamWaitEvent(0, evJ, 0);

    for (int l = 0; l < 3; l++) {
        if (l > 0)
            gemm_hmma_k<<<gemm_blocks, 256, GEMM_SMEM_H>>>(
                (const float*)p_agg, Wl[l],
                (const float*)p_stats + (size_t)(l - 1) * 2 * Hh, gl[l - 1], bel[l - 1]);
        gather_k<<<gather_blocks, 256>>>(bl[l], l);
    }

    pool2_k<<<Bb, Hh>>>(gl[2], bel[2]);
    mlp_k<<<Bb, 128>>>(gf, M1w, M1b, M2w, M2b, M3w, M3b, out);
}

// round 15
// speedup vs baseline: 1.1758x; 1.0475x over previous
#include <cuda_runtime.h>
#include <cuda_fp16.h>
#include <math.h>

#define Nn 50000
#define Ee 800000
#define Bb 512
#define Hh 128
#define Gg 32
#define EPSf 1e-5f

// ---------------- device scratch (static, no allocs) ----------------
__device__ __half g_hw16[(size_t)Nn * Hh]; // h @ W, fp16
__device__ float g_agg[(size_t)Nn * Hh];   // aggregated (pre-BN), fp32
__device__ float g_dinv[Nn];
__device__ int   g_deg[Nn];                // zeroed by scan_k after use
__device__ int   g_rowptr[Nn + 1];
__device__ int   g_cursor[Nn];
__device__ int2  g_csr2[Ee];               // {src, coef_bits}, bucketed by dst
__device__ int   g_bptr[Bb + 1];           // batch -> node range (batch is sorted)
__device__ float g_stats3[3][2 * Hh];      // per-layer [sum, sumsq]; zeroed by mlp_k
__device__ float g_pool[Bb * Hh];          // fully overwritten by pool2_k each call

// ---------------- degree / dinv ----------------
__global__ void deg_count_k(const int* __restrict__ dst) {
    int i = blockIdx.x * blockDim.x + threadIdx.x;
    if (i < Ee) atomicAdd(&g_deg[dst[i]], 1);
}

__global__ void dinv_k() {
    int i = blockIdx.x * blockDim.x + threadIdx.x;
    if (i < Nn) g_dinv[i] = rsqrtf((float)(g_deg[i] + 1));  // +1 self loop
}

// ---------------- batch rowptr (batch sorted): bptr[b] = first i with batch[i] >= b
__global__ void batch_ptr_k(const int* __restrict__ batch) {
    int i = blockIdx.x * blockDim.x + threadIdx.x;
    if (i > Nn) return;
    if (i == 0) {
        int b0 = batch[0];
        for (int b = 0; b <= b0; b++) g_bptr[b] = 0;
    } else if (i == Nn) {
        int bl = batch[Nn - 1];
        for (int b = bl + 1; b <= Bb; b++) g_bptr[b] = Nn;
    } else {
        int bp = batch[i - 1];
        int bc = batch[i];
        for (int b = bp + 1; b <= bc; b++) g_bptr[b] = i;
    }
}

// ---------------- prefix scan over degrees (single block) ----------------
__global__ void scan_k() {
    const int T = 1024;
    const int C = (Nn + T - 1) / T;
    int tid = threadIdx.x;
    int b0 = tid * C;
    int b1 = min(b0 + C, Nn);
    int s = 0;
    for (int i = b0; i < b1; i++) s += g_deg[i];
    __shared__ int sh[T];
    sh[tid] = s;
    __syncthreads();
    for (int o = 1; o < T; o <<= 1) {
        int v = (tid >= o) ? sh[tid - o] : 0;
        __syncthreads();
        sh[tid] += v;
        __syncthreads();
    }
    int run = (tid > 0) ? sh[tid - 1] : 0;
    for (int i = b0; i < b1; i++) {
        g_rowptr[i] = run;
        g_cursor[i] = run;
        int d = g_deg[i];
        g_deg[i] = 0;                     // self-clean for next call
        run += d;
    }
    if (tid == T - 1) g_rowptr[Nn] = run;
}

// ---------------- CSR fill: single packed {src, coef} store per edge ----------------
__global__ void fill_k(const int* __restrict__ src, const int* __restrict__ dst) {
    int e = blockIdx.x * blockDim.x + threadIdx.x;
    if (e >= Ee) return;
    int d = dst[e];
    int s = src[e];
    int pos = atomicAdd(&g_cursor[d], 1);
    float coef = g_dinv[s] * g_dinv[d];
    g_csr2[pos] = make_int2(s, __float_as_int(coef));
}

// ---------------- fused gather + self-loop + bias + BN stats ----------------
// R11/R13 skeleton; per-chunk: one coalesced int2 load (src+coef), shfl both.
__device__ __forceinline__ float4 ld_row16(const __half* row, int lane) {
    uint2 u = __ldg((const uint2*)row + lane);
    float2 f0 = __half22float2(*(__half2*)&u.x);
    float2 f1 = __half22float2(*(__half2*)&u.y);
    return make_float4(f0.x, f0.y, f1.x, f1.y);
}

#define NPW 8
__global__ void gather_k(const float* __restrict__ bias, int layer) {
    int tid = threadIdx.x;
    int lane = tid & 31;
    int wIn = tid >> 5;
    int gw = blockIdx.x * 8 + wIn;
    int n0 = gw * NPW;

    float4 bv = ((const float4*)bias)[lane];
    float bs0 = 0.f, bs1 = 0.f, bs2 = 0.f, bs3 = 0.f;
    float q0 = 0.f, q1 = 0.f, q2 = 0.f, q3 = 0.f;

    for (int nd = n0; nd < min(n0 + NPW, Nn); nd++) {
        float dd = g_dinv[nd];
        float self = dd * dd;
        float4 hv = ld_row16(g_hw16 + (size_t)nd * Hh, lane);
        float4 a0, a1, a2, a3;
        a0.x = fmaf(self, hv.x, bv.x);
        a0.y = fmaf(self, hv.y, bv.y);
        a0.z = fmaf(self, hv.z, bv.z);
        a0.w = fmaf(self, hv.w, bv.w);
        a1 = make_float4(0.f, 0.f, 0.f, 0.f);
        a2 = make_float4(0.f, 0.f, 0.f, 0.f);
        a3 = make_float4(0.f, 0.f, 0.f, 0.f);

        int ofs = g_rowptr[nd];
        int end = g_rowptr[nd + 1];
        for (int base = ofs; base < end; base += 32) {
            int cnt = min(32, end - base);
            int sidx = 0;
            float cfv = 0.f;
            if (lane < cnt) {
                int2 ed = __ldg(&g_csr2[base + lane]);   // one coalesced LDG.64
                sidx = ed.x;
                cfv = __int_as_float(ed.y);
            }
            int j = 0;
            for (; j + 8 <= cnt; j += 8) {
                int ss[8];
                float cc[8];
                #pragma unroll
                for (int u = 0; u < 8; u++) {
                    ss[u] = __shfl_sync(0xFFFFFFFFu, sidx, j + u);
                    cc[u] = __shfl_sync(0xFFFFFFFFu, cfv, j + u);
                }
                uint2 raw[8];
                #pragma unroll
                for (int u = 0; u < 8; u++)
                    raw[u] = __ldg((const uint2*)(g_hw16 + (size_t)ss[u] * Hh) + lane);
                #pragma unroll
                for (int u = 0; u < 8; u += 4) {
                    #pragma unroll
                    for (int w = 0; w < 4; w++) {
                        float2 f0 = __half22float2(*(__half2*)&raw[u + w].x);
                        float2 f1 = __half22float2(*(__half2*)&raw[u + w].y);
                        float c = cc[u + w];
                        float4* ap = (w == 0) ? &a0 : (w == 1) ? &a1 : (w == 2) ? &a2 : &a3;
                        ap->x = fmaf(c, f0.x, ap->x);
                        ap->y = fmaf(c, f0.y, ap->y);
                        ap->z = fmaf(c, f1.x, ap->z);
                        ap->w = fmaf(c, f1.y, ap->w);
                    }
                }
            }
            for (; j + 4 <= cnt; j += 4) {
                int s0 = __shfl_sync(0xFFFFFFFFu, sidx, j + 0);
                int s1 = __shfl_sync(0xFFFFFFFFu, sidx, j + 1);
                int s2 = __shfl_sync(0xFFFFFFFFu, sidx, j + 2);
                int s3 = __shfl_sync(0xFFFFFFFFu, sidx, j + 3);
                float c0 = __shfl_sync(0xFFFFFFFFu, cfv, j + 0);
                float c1 = __shfl_sync(0xFFFFFFFFu, cfv, j + 1);
                float c2 = __shfl_sync(0xFFFFFFFFu, cfv, j + 2);
                float c3 = __shfl_sync(0xFFFFFFFFu, cfv, j + 3);
                float4 v0 = ld_row16(g_hw16 + (size_t)s0 * Hh, lane);
                float4 v1 = ld_row16(g_hw16 + (size_t)s1 * Hh, lane);
                float4 v2 = ld_row16(g_hw16 + (size_t)s2 * Hh, lane);
                float4 v3 = ld_row16(g_hw16 + (size_t)s3 * Hh, lane);
                a0.x = fmaf(c0, v0.x, a0.x); a0.y = fmaf(c0, v0.y, a0.y);
                a0.z = fmaf(c0, v0.z, a0.z); a0.w = fmaf(c0, v0.w, a0.w);
                a1.x = fmaf(c1, v1.x, a1.x); a1.y = fmaf(c1, v1.y, a1.y);
                a1.z = fmaf(c1, v1.z, a1.z); a1.w = fmaf(c1, v1.w, a1.w);
                a2.x = fmaf(c2, v2.x, a2.x); a2.y = fmaf(c2, v2.y, a2.y);
                a2.z = fmaf(c2, v2.z, a2.z); a2.w = fmaf(c2, v2.w, a2.w);
                a3.x = fmaf(c3, v3.x, a3.x); a3.y = fmaf(c3, v3.y, a3.y);
                a3.z = fmaf(c3, v3.z, a3.z); a3.w = fmaf(c3, v3.w, a3.w);
            }
            for (; j < cnt; j++) {
                int s = __shfl_sync(0xFFFFFFFFu, sidx, j);
                float c = __shfl_sync(0xFFFFFFFFu, cfv, j);
                float4 v = ld_row16(g_hw16 + (size_t)s * Hh, lane);
                a0.x = fmaf(c, v.x, a0.x);
                a0.y = fmaf(c, v.y, a0.y);
                a0.z = fmaf(c, v.z, a0.z);
                a0.w = fmaf(c, v.w, a0.w);
            }
        }
        float4 acc;
        acc.x = (a0.x + a1.x) + (a2.x + a3.x);
        acc.y = (a0.y + a1.y) + (a2.y + a3.y);
        acc.z = (a0.z + a1.z) + (a2.z + a3.z);
        acc.w = (a0.w + a1.w) + (a2.w + a3.w);
        ((float4*)(g_agg + (size_t)nd * Hh))[lane] = acc;

        bs0 += acc.x; bs1 += acc.y; bs2 += acc.z; bs3 += acc.w;
        q0 = fmaf(acc.x, acc.x, q0);
        q1 = fmaf(acc.y, acc.y, q1);
        q2 = fmaf(acc.z, acc.z, q2);
        q3 = fmaf(acc.w, acc.w, q3);
    }

    __shared__ float s_sum[Hh];
    __shared__ float s_ss[Hh];
    if (tid < Hh) { s_sum[tid] = 0.f; s_ss[tid] = 0.f; }
    __syncthreads();
    int c0i = lane * 4;
    atomicAdd(&s_sum[c0i + 0], bs0); atomicAdd(&s_ss[c0i + 0], q0);
    atomicAdd(&s_sum[c0i + 1], bs1); atomicAdd(&s_ss[c0i + 1], q1);
    atomicAdd(&s_sum[c0i + 2], bs2); atomicAdd(&s_ss[c0i + 2], q2);
    atomicAdd(&s_sum[c0i + 3], bs3); atomicAdd(&s_ss[c0i + 3], q3);
    __syncthreads();
    if (tid < Hh) {
        atomicAdd(&g_stats3[layer][tid], s_sum[tid]);
        atomicAdd(&g_stats3[layer][Hh + tid], s_ss[tid]);
    }
}

// ---------------- HMMA GEMM with in-kernel BN (from stats) ----------------
#define KS 136
#define GEMM_SMEM_H (2 * 128 * KS * (int)sizeof(__half))

__global__ void __launch_bounds__(256, 1)
gemm_hmma_k(const float* __restrict__ in, const float* __restrict__ W,
            const float* __restrict__ stats,      // null -> no BN
            const float* __restrict__ gamma, const float* __restrict__ beta) {
    extern __shared__ __half smh[];
    __half* As = smh;              // [128][KS]
    __half* Bs = smh + 128 * KS;   // [128][KS]
    __shared__ float sa[Hh], sc[Hh];
    int tid = threadIdx.x;
    int row0 = blockIdx.x * 128;

    if (stats) {
        if (tid < Hh) {
            float s = stats[tid], ss = stats[Hh + tid];
            float mean = s / (float)Nn;
            float var = ss / (float)Nn - mean * mean;
            float a = gamma[tid] * rsqrtf(var + EPSf);
            sa[tid] = a;
            sc[tid] = beta[tid] - mean * a;
        }
        __syncthreads();
    }

    // ---- load A: thread t handles row r=t>>1, cols 64*(t&1)..+63 ----
    {
        int r = tid >> 1;
        int ch = (tid & 1) * 64;
        int grow = row0 + r;
        __half* arow = As + r * KS + ch;
        if (grow < Nn) {
            const float4* rp = (const float4*)(in + (size_t)grow * Hh + ch);
            #pragma unroll
            for (int it = 0; it < 8; it++) {
                float4 v0 = __ldg(rp + it * 2);
                float4 v1 = __ldg(rp + it * 2 + 1);
                if (stats) {
                    int q = ch + it * 8;
                    float4 av0 = *(const float4*)(sa + q);
                    float4 cv0 = *(const float4*)(sc + q);
                    float4 av1 = *(const float4*)(sa + q + 4);
                    float4 cv1 = *(const float4*)(sc + q + 4);
                    v0.x = fmaxf(fmaf(v0.x, av0.x, cv0.x), 0.f);
                    v0.y = fmaxf(fmaf(v0.y, av0.y, cv0.y), 0.f);
                    v0.z = fmaxf(fmaf(v0.z, av0.z, cv0.z), 0.f);
                    v0.w = fmaxf(fmaf(v0.w, av0.w, cv0.w), 0.f);
                    v1.x = fmaxf(fmaf(v1.x, av1.x, cv1.x), 0.f);
                    v1.y = fmaxf(fmaf(v1.y, av1.y, cv1.y), 0.f);
                    v1.z = fmaxf(fmaf(v1.z, av1.z, cv1.z), 0.f);
                    v1.w = fmaxf(fmaf(v1.w, av1.w, cv1.w), 0.f);
                }
                __half2 h0 = __floats2half2_rn(v0.x, v0.y);
                __half2 h1 = __floats2half2_rn(v0.z, v0.w);
                __half2 h2 = __floats2half2_rn(v1.x, v1.y);
                __half2 h3 = __floats2half2_rn(v1.z, v1.w);
                uint4 o;
                o.x = *(unsigned*)&h0; o.y = *(unsigned*)&h1;
                o.z = *(unsigned*)&h2; o.w = *(unsigned*)&h3;
                *(uint4*)(arow + it * 8) = o;
            }
        } else {
            uint4 z = make_uint4(0, 0, 0, 0);
            #pragma unroll
            for (int it = 0; it < 8; it++) *(uint4*)(arow + it * 8) = z;
        }
    }

    // ---- load B = W^T: thread t: n = t&127, k range 64*(t>>7)..+63 ----
    {
        int n = tid & 127;
        int k0 = (tid >> 7) * 64;
        __half* brow = Bs + n * KS;
        #pragma unroll 8
        for (int k = k0; k < k0 + 64; k += 2) {
            float w0 = __ldg(W + (size_t)k * Hh + n);
            float w1 = __ldg(W + (size_t)(k + 1) * Hh + n);
            __half2 h = __floats2half2_rn(w0, w1);
            *(unsigned*)(brow + k) = *(unsigned*)&h;
        }
    }

    __syncthreads();

    // ---- compute ----
    int lane = tid & 31;
    int wrp = tid >> 5;
    int gid = lane >> 2;
    int tg = lane & 3;
    int m0 = wrp * 16;

    float c[16][4];
    #pragma unroll
    for (int nt = 0; nt < 16; nt++)
        #pragma unroll
        for (int i = 0; i < 4; i++) c[nt][i] = 0.f;

    const __half* aR0 = As + (m0 + gid) * KS + 2 * tg;
    const __half* aR1 = As + (m0 + gid + 8) * KS + 2 * tg;

    #pragma unroll
    for (int ki = 0; ki < 8; ki++) {
        int k0 = ki * 16;
        unsigned a0 = *(const unsigned*)(aR0 + k0);
        unsigned a1 = *(const unsigned*)(aR1 + k0);
        unsigned a2 = *(const unsigned*)(aR0 + k0 + 8);
        unsigned a3 = *(const unsigned*)(aR1 + k0 + 8);
        #pragma unroll
        for (int nt = 0; nt < 16; nt++) {
            const __half* bR = Bs + (nt * 8 + gid) * KS + 2 * tg;
            unsigned b0 = *(const unsigned*)(bR + k0);
            unsigned b1 = *(const unsigned*)(bR + k0 + 8);
            asm volatile(
                "mma.sync.aligned.m16n8k16.row.col.f32.f16.f16.f32 "
                "{%0,%1,%2,%3}, {%4,%5,%6,%7}, {%8,%9}, {%0,%1,%2,%3};"
                : "+f"(c[nt][0]), "+f"(c[nt][1]), "+f"(c[nt][2]), "+f"(c[nt][3])
                : "r"(a0), "r"(a1), "r"(a2), "r"(a3), "r"(b0), "r"(b1));
        }
    }

    // ---- epilogue: fp32 acc -> fp16 g_hw16 ----
    int r0g = row0 + m0 + gid;
    int r1g = r0g + 8;
    #pragma unroll
    for (int nt = 0; nt < 16; nt++) {
        int col = nt * 8 + 2 * tg;
        if (r0g < Nn) {
            __half2 h = __floats2half2_rn(c[nt][0], c[nt][1]);
            *(unsigned*)(g_hw16 + (size_t)r0g * Hh + col) = *(unsigned*)&h;
        }
        if (r1g < Nn) {
            __half2 h = __floats2half2_rn(c[nt][2], c[nt][3]);
            *(unsigned*)(g_hw16 + (size_t)r1g * Hh + col) = *(unsigned*)&h;
        }
    }
}

// ---------------- pooling: segmented reduction over sorted batch (no atomics) ----------------
__global__ void pool2_k(const float* __restrict__ gamma, const float* __restrict__ beta) {
    __shared__ float sa[Hh], sc[Hh];
    int b = blockIdx.x;
    int tid = threadIdx.x;   // 128 threads, one per column
    {
        float s = g_stats3[2][tid], ss = g_stats3[2][Hh + tid];
        float mean = s / (float)Nn;
        float var = ss / (float)Nn - mean * mean;
        float a = gamma[tid] * rsqrtf(var + EPSf);
        sa[tid] = a;
        sc[tid] = beta[tid] - mean * a;
    }
    __syncthreads();

    int r0 = g_bptr[b];
    int r1 = g_bptr[b + 1];
    float a = sa[tid], cs = sc[tid];
    float acc0 = 0.f, acc1 = 0.f;
    int r = r0;
    for (; r + 2 <= r1; r += 2) {
        float v0 = g_agg[(size_t)r * Hh + tid];
        float v1 = g_agg[(size_t)(r + 1) * Hh + tid];
        acc0 += fmaxf(fmaf(v0, a, cs), 0.f);
        acc1 += fmaxf(fmaf(v1, a, cs), 0.f);
    }
    if (r < r1) acc0 += fmaxf(fmaf(g_agg[(size_t)r * Hh + tid], a, cs), 0.f);
    float cnt = fmaxf((float)(r1 - r0), 1.0f);
    g_pool[(size_t)b * Hh + tid] = (acc0 + acc1) / cnt;
}

// ---------------- MLP head (self-cleans stats) ----------------
__global__ void mlp_k(const float* __restrict__ gf,
                      const float* __restrict__ M1w, const float* __restrict__ M1b,
                      const float* __restrict__ M2w, const float* __restrict__ M2b,
                      const float* __restrict__ M3w, const float* __restrict__ M3b,
                      float* __restrict__ out) {
    __shared__ float z[Hh + Gg];
    __shared__ float z1[128];
    __shared__ float z2[64];
    int b = blockIdx.x;
    int tid = threadIdx.x;
    if (b < 6 && tid < Hh) ((float*)g_stats3)[b * Hh + tid] = 0.f;   // zero 3x256 stats
    if (tid < Hh) z[tid] = g_pool[(size_t)b * Hh + tid];
    if (tid < Gg) z[Hh + tid] = gf[(size_t)b * Gg + tid];
    __syncthreads();
    {
        float acc = M1b[tid];
        #pragma unroll 4
        for (int k = 0; k < Hh + Gg; k++) acc = fmaf(z[k], M1w[k * 128 + tid], acc);
        z1[tid] = fmaxf(acc, 0.f);
    }
    __syncthreads();
    if (tid < 64) {
        float acc = M2b[tid];
        #pragma unroll 4
        for (int k = 0; k < 128; k++) acc = fmaf(z1[k], M2w[k * 64 + tid], acc);
        z2[tid] = fmaxf(acc, 0.f);
    }
    __syncthreads();
    if (tid == 0) {
        float acc = M3b[0];
        #pragma unroll 4
        for (int k = 0; k < 64; k++) acc = fmaf(z2[k], M3w[k], acc);
        out[b] = acc;
    }
}

// ---------------- host launch ----------------
extern "C" void kernel_launch(void* const* d_in, const int* in_sizes, int n_in,
                              void* d_out, int out_size) {
    const float* x   = (const float*)d_in[0];
    const int*   ei  = (const int*)d_in[1];
    const int*   batch = (const int*)d_in[2];
    const float* gf  = (const float*)d_in[3];
    const float* Wl[3]  = { (const float*)d_in[4],  (const float*)d_in[8],  (const float*)d_in[12] };
    const float* bl[3]  = { (const float*)d_in[5],  (const float*)d_in[9],  (const float*)d_in[13] };
    const float* gl[3]  = { (const float*)d_in[6],  (const float*)d_in[10], (const float*)d_in[14] };
    const float* bel[3] = { (const float*)d_in[7],  (const float*)d_in[11], (const float*)d_in[15] };
    const float* M1w = (const float*)d_in[16];
    const float* M1b = (const float*)d_in[17];
    const float* M2w = (const float*)d_in[18];
    const float* M2b = (const float*)d_in[19];
    const float* M3w = (const float*)d_in[20];
    const float* M3b = (const float*)d_in[21];
    float* out = (float*)d_out;

    const int* src = ei;
    const int* dst = ei + Ee;

    void *p_agg, *p_stats;
    cudaGetSymbolAddress(&p_agg, g_agg);
    cudaGetSymbolAddress(&p_stats, g_stats3);

    static int inited = 0;
    static cudaStream_t s2;
    static cudaEvent_t evF, evJ;
    if (!inited) {
        cudaFuncSetAttribute(gemm_hmma_k, cudaFuncAttributeMaxDynamicSharedMemorySize, GEMM_SMEM_H);
        cudaStreamCreateWithFlags(&s2, cudaStreamNonBlocking);
        cudaEventCreateWithFlags(&evF, cudaEventDisableTiming);
        cudaEventCreateWithFlags(&evJ, cudaEventDisableTiming);
        inited = 1;
    }

    const int gemm_blocks = (Nn + 127) / 128;                  // 391
    const int gather_blocks = (Nn + 8 * NPW - 1) / (8 * NPW);
    const int bptr_blocks = (Nn + 1 + 255) / 256;

    // Fork: CSR build + batch rowptr on side stream, layer-0 GEMM on main stream.
    cudaEventRecord(evF, 0);
    cudaStreamWaitEvent(s2, evF, 0);
    deg_count_k<<<(Ee + 255) / 256, 256, 0, s2>>>(dst);
    dinv_k<<<(Nn + 255) / 256, 256, 0, s2>>>();
    scan_k<<<1, 1024, 0, s2>>>();
    fill_k<<<(Ee + 255) / 256, 256, 0, s2>>>(src, dst);
    batch_ptr_k<<<bptr_blocks, 256, 0, s2>>>(batch);

    gemm_hmma_k<<<gemm_blocks, 256, GEMM_SMEM_H>>>(x, Wl[0], 0, 0, 0);

    cudaEventRecord(evJ, s2);
    cudaStreamWaitEvent(0, evJ, 0);

    for (int l = 0; l < 3; l++) {
        if (l > 0)
            gemm_hmma_k<<<gemm_blocks, 256, GEMM_SMEM_H>>>(
                (const float*)p_agg, Wl[l],
                (const float*)p_stats + (size_t)(l - 1) * 2 * Hh, gl[l - 1], bel[l - 1]);
        gather_k<<<gather_blocks, 256>>>(bl[l], l);
    }

    pool2_k<<<Bb, Hh>>>(gl[2], bel[2]);
    mlp_k<<<Bb, 128>>>(gf, M1w, M1b, M2w, M2b, M3w, M3b, out);
}